// round 1
// baseline (speedup 1.0000x reference)
#include <cuda_runtime.h>

// EdgeEmbAttentionAggregator — fused GAT-style aggregation, fp32 baseline.
// x = input@W ; neighs = (neigh_feat@W2) ; scores = x.a_x + neighs.a_n + ee.a_e
// leaky_relu(0.8) -> softmax over S=16 -> h' = att.neighs, h_e = att.ee
// out = [x | h' | h_e]  (N x 160, fp32)

namespace {

constexpr int S    = 16;
constexpr int IND  = 128;
constexpr int D    = 64;
constexpr int E    = 32;
constexpr int B    = 8;              // nodes per CTA
constexpr int ROWS = B * S;          // 128 neighbor rows per CTA
constexpr int THREADS = 256;
constexpr int OUTD = D + D + E;      // 160
constexpr float LRELU_ALPHA = 0.8f;

// padded smem strides (bank-conflict avoidance)
constexpr int ST_NB  = IND + 2;      // 130: 4-row groups land on banks {0,8,16,24}
constexpr int ST_EE  = E + 2;        // 34
constexpr int ST_NBH = D + 2;        // 66

constexpr int SMEM_FLOATS =
    IND*D            // W
  + IND*D            // W2
  + OUTD             // a
  + ROWS*ST_NB       // staged neigh tile
  + ROWS*ST_EE       // staged edge tile
  + ROWS*ST_NBH      // transformed neighbors
  + B*IND            // staged input rows
  + B                // s_x per node
  + ROWS             // scores
  + ROWS             // attention
  + B*OUTD;          // output staging
constexpr int SMEM_BYTES = SMEM_FLOATS * 4;

typedef unsigned long long ull;

// packed f32x2 FMA — sm_103a only emits FFMA2 via explicit PTX
__device__ __forceinline__ ull ffma2(ull a, ull b, ull c) {
    ull d;
    asm("fma.rn.f32x2 %0, %1, %2, %3;" : "=l"(d) : "l"(a), "l"(b), "l"(c));
    return d;
}
__device__ __forceinline__ ull splat2(float x) {
    ull r;
    asm("mov.b64 %0, {%1, %1};" : "=l"(r) : "f"(x));
    return r;
}

} // namespace

__global__ void __launch_bounds__(THREADS, 1)
gat_fused_kernel(const float* __restrict__ gIn,
                 const float* __restrict__ gNb,
                 const float* __restrict__ gEe,
                 const float* __restrict__ gW,
                 const float* __restrict__ gW2,
                 const float* __restrict__ gA,
                 float* __restrict__ gOut,
                 int N)
{
    extern __shared__ float sm[];
    float* sW   = sm;
    float* sW2  = sW   + IND*D;
    float* sA   = sW2  + IND*D;
    float* sNb  = sA   + OUTD;
    float* sEe  = sNb  + ROWS*ST_NB;
    float* sNbh = sEe  + ROWS*ST_EE;
    float* sIn  = sNbh + ROWS*ST_NBH;
    float* sSxa = sIn  + B*IND;
    float* sSc  = sSxa + B;
    float* sAtt = sSc  + ROWS;
    float* sOut = sAtt + ROWS;

    const int tid    = threadIdx.x;
    const int node0  = blockIdx.x * B;
    const int vnodes = min(B, N - node0);
    const int vrows  = vnodes * S;

    // ---------------- load weights (L2-hot across CTAs) ----------------
    {
        const float4* w4  = reinterpret_cast<const float4*>(gW);
        const float4* w24 = reinterpret_cast<const float4*>(gW2);
        float4* dW  = reinterpret_cast<float4*>(sW);
        float4* dW2 = reinterpret_cast<float4*>(sW2);
        for (int i = tid; i < IND*D/4; i += THREADS) { dW[i] = w4[i]; dW2[i] = w24[i]; }
        if (tid < OUTD) sA[tid] = gA[tid];
    }

    // ---------------- stage node-block tiles (all contiguous in gmem) ----------------
    {
        const float4* nb4 = reinterpret_cast<const float4*>(gNb) + (size_t)node0 * S * (IND/4);
        for (int i = tid; i < ROWS*IND/4; i += THREADS) {
            int row = i >> 5;                        // 32 float4 per row
            float4 v = (row < vrows) ? nb4[i] : make_float4(0.f,0.f,0.f,0.f);
            int k = (i & 31) << 2;
            float* p = sNb + row*ST_NB + k;          // ST_NB even -> float2 aligned
            *reinterpret_cast<float2*>(p)     = make_float2(v.x, v.y);
            *reinterpret_cast<float2*>(p + 2) = make_float2(v.z, v.w);
        }
        const float4* ee4 = reinterpret_cast<const float4*>(gEe) + (size_t)node0 * S * (E/4);
        for (int i = tid; i < ROWS*E/4; i += THREADS) {
            int row = i >> 3;                        // 8 float4 per row
            float4 v = (row < vrows) ? ee4[i] : make_float4(0.f,0.f,0.f,0.f);
            int c = (i & 7) << 2;
            float* p = sEe + row*ST_EE + c;
            *reinterpret_cast<float2*>(p)     = make_float2(v.x, v.y);
            *reinterpret_cast<float2*>(p + 2) = make_float2(v.z, v.w);
        }
        const float4* in4 = reinterpret_cast<const float4*>(gIn) + (size_t)node0 * (IND/4);
        float4* dIn = reinterpret_cast<float4*>(sIn);
        for (int i = tid; i < B*IND/4; i += THREADS) {
            int row = i >> 5;
            dIn[i] = (row < vnodes) ? in4[i] : make_float4(0.f,0.f,0.f,0.f);
        }
    }
    __syncthreads();

    // ---------------- neighbor GEMM: (128x128)@(128x64), 4x8 micro-tile, f32x2 ----------------
    const int rg = tid >> 3;          // 0..31 row-group
    const int cg = tid & 7;           // 0..7 col-group
    const int R  = rg << 2;           // 4 rows
    const int C  = cg << 3;           // 8 cols (4 packed pairs)

    ull acc[4][4];
    #pragma unroll
    for (int i = 0; i < 4; i++)
        #pragma unroll
        for (int j = 0; j < 4; j++) acc[i][j] = 0ull;   // bits of (0.f, 0.f)

    const float* aBase = sNb + R*ST_NB;
    #pragma unroll 4
    for (int k = 0; k < IND; k++) {
        const ulonglong2* bp = reinterpret_cast<const ulonglong2*>(sW2 + k*D + C);
        ulonglong2 b0 = bp[0];   // cols C..C+3 as 2 packed pairs
        ulonglong2 b1 = bp[1];   // cols C+4..C+7
        #pragma unroll
        for (int i = 0; i < 4; i++) {
            ull av = splat2(aBase[i*ST_NB + k]);
            acc[i][0] = ffma2(av, b0.x, acc[i][0]);
            acc[i][1] = ffma2(av, b0.y, acc[i][1]);
            acc[i][2] = ffma2(av, b1.x, acc[i][2]);
            acc[i][3] = ffma2(av, b1.y, acc[i][3]);
        }
    }
    #pragma unroll
    for (int i = 0; i < 4; i++)
        #pragma unroll
        for (int j = 0; j < 4; j++)
            *reinterpret_cast<ull*>(sNbh + (R+i)*ST_NBH + C + 2*j) = acc[i][j];

    // ---------------- x = input @ W (each thread: 2 output elems) ----------------
    {
        const int c  = tid & 63;
        const int r0 = tid >> 6;      // 0..3
        const int r1 = r0 + 4;        // 4..7
        float x0 = 0.f, x1 = 0.f;
        const float* in0 = sIn + r0*IND;
        const float* in1 = sIn + r1*IND;
        #pragma unroll 8
        for (int k = 0; k < IND; k++) {
            float b = sW[k*D + c];
            x0 += in0[k] * b;
            x1 += in1[k] * b;
        }
        sOut[r0*OUTD + c] = x0;
        sOut[r1*OUTD + c] = x1;
    }
    __syncthreads();

    // ---------------- s_x = x . a_x per node ----------------
    if (tid < B) {
        float s = 0.f;
        #pragma unroll 8
        for (int c = 0; c < D; c++) s += sOut[tid*OUTD + c] * sA[c];
        sSxa[tid] = s;
    }
    __syncthreads();

    // ---------------- scores + leaky relu ----------------
    if (tid < ROWS) {
        float s = sSxa[tid >> 4];
        const float* nh = sNbh + tid*ST_NBH;
        #pragma unroll 8
        for (int c = 0; c < D; c++) s += nh[c] * sA[D + c];
        const float* ee = sEe + tid*ST_EE;
        #pragma unroll 8
        for (int c = 0; c < E; c++) s += ee[c] * sA[2*D + c];
        sSc[tid] = (s > 0.f) ? s : LRELU_ALPHA * s;
    }
    __syncthreads();

    // ---------------- softmax over S neighbors (one thread per node) ----------------
    if (tid < B && tid < vnodes) {
        const float* sc = sSc + tid*S;
        float m = sc[0];
        #pragma unroll
        for (int s = 1; s < S; s++) m = fmaxf(m, sc[s]);
        float ex[S];
        float den = 0.f;
        #pragma unroll
        for (int s = 0; s < S; s++) { ex[s] = expf(sc[s] - m); den += ex[s]; }
        float inv = 1.f / den;
        #pragma unroll
        for (int s = 0; s < S; s++) sAtt[tid*S + s] = ex[s] * inv;
    }
    __syncthreads();

    // ---------------- h_prime = att . neighs ----------------
    for (int e = tid; e < B*D; e += THREADS) {
        int n = e >> 6, c = e & 63;
        const float* at = sAtt + n*S;
        const float* nh = sNbh + n*S*ST_NBH + c;
        float h = 0.f;
        #pragma unroll
        for (int s = 0; s < S; s++) h += at[s] * nh[s*ST_NBH];
        sOut[n*OUTD + D + c] = h;
    }
    // ---------------- h_edge = att . ee ----------------
    if (tid < B*E) {
        int n = tid >> 5, c = tid & 31;
        const float* at = sAtt + n*S;
        const float* ee = sEe + n*S*ST_EE + c;
        float h = 0.f;
        #pragma unroll
        for (int s = 0; s < S; s++) h += at[s] * ee[s*ST_EE];
        sOut[n*OUTD + 2*D + c] = h;
    }
    __syncthreads();

    // ---------------- coalesced output write ----------------
    {
        float4* o4 = reinterpret_cast<float4*>(gOut) + (size_t)node0 * (OUTD/4);
        const float4* s4 = reinterpret_cast<const float4*>(sOut);
        const int lim = vnodes * (OUTD/4);
        for (int i = tid; i < lim; i += THREADS) o4[i] = s4[i];
    }
}

extern "C" void kernel_launch(void* const* d_in, const int* in_sizes, int n_in,
                              void* d_out, int out_size)
{
    const float* gIn = (const float*)d_in[0];   // input      (N, 128)
    const float* gNb = (const float*)d_in[1];   // neigh_feat (N*16, 128)
    const float* gEe = (const float*)d_in[2];   // edge_emb   (N*16, 32)
    const float* gW  = (const float*)d_in[3];   // W  (128, 64)
    const float* gW2 = (const float*)d_in[4];   // W2 (128, 64)
    const float* gA  = (const float*)d_in[5];   // a  (160, 1)
    float* gOut = (float*)d_out;                // (N, 160)

    const int N = in_sizes[0] / IND;

    cudaFuncSetAttribute(gat_fused_kernel,
                         cudaFuncAttributeMaxDynamicSharedMemorySize, SMEM_BYTES);
    const int grid = (N + B - 1) / B;
    gat_fused_kernel<<<grid, THREADS, SMEM_BYTES>>>(gIn, gNb, gEe, gW, gW2, gA, gOut, N);
}

// round 2
// speedup vs baseline: 1.7504x; 1.7504x over previous
#include <cuda_runtime.h>

// EdgeEmbAttentionAggregator — fused GAT aggregation, fp32, round 2.
// Changes vs R1: smem 190KB -> 91KB (2 CTAs/SM), GEMM A-operand streamed from
// global with register double-buffering, x-GEMM one-warp-per-node with fused
// s_x shuffle reduction, shuffle-based softmax.

namespace {

constexpr int S    = 16;
constexpr int IND  = 128;
constexpr int D    = 64;
constexpr int E    = 32;
constexpr int B    = 8;              // nodes per CTA
constexpr int ROWS = B * S;          // 128 neighbor rows per CTA
constexpr int THREADS = 256;
constexpr int OUTD = D + D + E;      // 160
constexpr float LRELU_ALPHA = 0.8f;

constexpr int ST_EE  = E + 2;        // 34
constexpr int ST_NBH = D + 2;        // 66

constexpr int SMEM_FLOATS =
    IND*D            // W2
  + OUTD             // a
  + ROWS*ST_EE       // staged edge tile
  + ROWS*ST_NBH      // transformed neighbors
  + B                // s_x per node
  + ROWS             // attention
  + B*OUTD;          // output staging
constexpr int SMEM_BYTES = SMEM_FLOATS * 4;   // ~90.3 KB

typedef unsigned long long ull;

__device__ __forceinline__ ull ffma2(ull a, ull b, ull c) {
    ull d;
    asm("fma.rn.f32x2 %0, %1, %2, %3;" : "=l"(d) : "l"(a), "l"(b), "l"(c));
    return d;
}
__device__ __forceinline__ ull splat2(float x) {
    ull r;
    asm("mov.b64 %0, {%1, %1};" : "=l"(r) : "f"(x));
    return r;
}
__device__ __forceinline__ float2 unpack2(ull v) {
    float lo, hi;
    asm("mov.b64 {%0, %1}, %2;" : "=f"(lo), "=f"(hi) : "l"(v));
    return make_float2(lo, hi);
}

} // namespace

__global__ void __launch_bounds__(THREADS, 2)
gat_fused_kernel(const float* __restrict__ gIn,
                 const float* __restrict__ gNb,
                 const float* __restrict__ gEe,
                 const float* __restrict__ gW,
                 const float* __restrict__ gW2,
                 const float* __restrict__ gA,
                 float* __restrict__ gOut,
                 int N)
{
    extern __shared__ float sm[];
    float* sW2  = sm;
    float* sA   = sW2  + IND*D;
    float* sEe  = sA   + OUTD;
    float* sNbh = sEe  + ROWS*ST_EE;
    float* sSxa = sNbh + ROWS*ST_NBH;
    float* sAtt = sSxa + B;
    float* sOut = sAtt + ROWS;

    const int tid    = threadIdx.x;
    const int node0  = blockIdx.x * B;
    const int vnodes = min(B, N - node0);
    const int vrows  = vnodes * S;

    // ---------------- phase 0: stage W2, a, edge tile ----------------
    {
        const float4* w24 = reinterpret_cast<const float4*>(gW2);
        float4* dW2 = reinterpret_cast<float4*>(sW2);
        #pragma unroll
        for (int i = 0; i < IND*D/4/THREADS; i++)
            dW2[tid + i*THREADS] = w24[tid + i*THREADS];
        if (tid < OUTD) sA[tid] = gA[tid];

        const float4* ee4 = reinterpret_cast<const float4*>(gEe) + (size_t)node0 * S * (E/4);
        #pragma unroll
        for (int t = 0; t < ROWS*E/4/THREADS; t++) {
            int i = tid + t*THREADS;
            int row = i >> 3;
            float4 v = (row < vrows) ? ee4[i] : make_float4(0.f,0.f,0.f,0.f);
            int c = (i & 7) << 2;
            float* p = sEe + row*ST_EE + c;
            *reinterpret_cast<float2*>(p)     = make_float2(v.x, v.y);
            *reinterpret_cast<float2*>(p + 2) = make_float2(v.z, v.w);
        }
    }
    __syncthreads();

    // ---------------- phase 1: neighbor GEMM (128x128)@(128x64) ----------------
    // A streamed from global, double-buffered float4; B from smem; f32x2 acc.
    {
        const int rg = tid >> 3;          // 0..31
        const int cg = tid & 7;           // 0..7
        const int R  = rg << 2;
        const int C  = cg << 3;

        const float* ar[4];
        #pragma unroll
        for (int i = 0; i < 4; i++) {
            int r = min(R + i, vrows - 1);
            ar[i] = gNb + ((size_t)node0 * S + r) * IND;
        }

        ull acc[4][4];
        #pragma unroll
        for (int i = 0; i < 4; i++)
            #pragma unroll
            for (int j = 0; j < 4; j++) acc[i][j] = 0ull;

        float4 cur[4], nxt[4];
        #pragma unroll
        for (int i = 0; i < 4; i++)
            cur[i] = *reinterpret_cast<const float4*>(ar[i]);

        #pragma unroll 2
        for (int kk = 0; kk < IND; kk += 4) {
            if (kk + 4 < IND) {
                #pragma unroll
                for (int i = 0; i < 4; i++)
                    nxt[i] = *reinterpret_cast<const float4*>(ar[i] + kk + 4);
            }
            #pragma unroll
            for (int j = 0; j < 4; j++) {
                const int k = kk + j;
                const ulonglong2* bp = reinterpret_cast<const ulonglong2*>(sW2 + k*D + C);
                ulonglong2 b0 = bp[0];
                ulonglong2 b1 = bp[1];
                #pragma unroll
                for (int i = 0; i < 4; i++) {
                    const float* cf = reinterpret_cast<const float*>(&cur[i]);
                    ull av = splat2(cf[j]);
                    acc[i][0] = ffma2(av, b0.x, acc[i][0]);
                    acc[i][1] = ffma2(av, b0.y, acc[i][1]);
                    acc[i][2] = ffma2(av, b1.x, acc[i][2]);
                    acc[i][3] = ffma2(av, b1.y, acc[i][3]);
                }
            }
            #pragma unroll
            for (int i = 0; i < 4; i++) cur[i] = nxt[i];
        }
        #pragma unroll
        for (int i = 0; i < 4; i++)
            #pragma unroll
            for (int j = 0; j < 4; j++)
                *reinterpret_cast<ull*>(sNbh + (R+i)*ST_NBH + C + 2*j) = acc[i][j];
    }

    // ---------------- phase 2: x = input@W, one warp per node, fused s_x ----------------
    {
        const int r = tid >> 5;           // node 0..7 (warp id)
        const int p = tid & 31;           // column pair
        const int nrow = min(node0 + r, N - 1);
        const float* inRow = gIn + (size_t)nrow * IND;

        ull xacc = 0ull;
        #pragma unroll 8
        for (int k = 0; k < IND; k++) {
            ull b = *reinterpret_cast<const ull*>(gW + k*D + 2*p);
            ull a2 = splat2(inRow[k]);
            xacc = ffma2(a2, b, xacc);
        }
        float2 xv = unpack2(xacc);
        *reinterpret_cast<float2*>(sOut + r*OUTD + 2*p) = xv;

        // s_x = x . a_x, warp reduction
        float part = xv.x * sA[2*p] + xv.y * sA[2*p + 1];
        #pragma unroll
        for (int off = 16; off > 0; off >>= 1)
            part += __shfl_xor_sync(0xffffffffu, part, off);
        if (p == 0) sSxa[r] = part;
    }
    __syncthreads();

    // ---------------- phase 3: scores + leaky relu + shuffle softmax ----------------
    if (tid < ROWS) {
        float s0 = sSxa[tid >> 4], s1 = 0.f, s2 = 0.f, s3 = 0.f;
        const float* nh = sNbh + tid*ST_NBH;
        const float* aN = sA + D;
        #pragma unroll
        for (int c = 0; c < D; c += 4) {
            s0 += nh[c+0] * aN[c+0];
            s1 += nh[c+1] * aN[c+1];
            s2 += nh[c+2] * aN[c+2];
            s3 += nh[c+3] * aN[c+3];
        }
        const float* ee = sEe + tid*ST_EE;
        const float* aE = sA + 2*D;
        #pragma unroll
        for (int c = 0; c < E; c += 4) {
            s0 += ee[c+0] * aE[c+0];
            s1 += ee[c+1] * aE[c+1];
            s2 += ee[c+2] * aE[c+2];
            s3 += ee[c+3] * aE[c+3];
        }
        float s = (s0 + s1) + (s2 + s3);
        s = (s > 0.f) ? s : LRELU_ALPHA * s;

        // softmax across the 16-lane segment (one node per half-warp)
        float m = s;
        #pragma unroll
        for (int off = 8; off > 0; off >>= 1)
            m = fmaxf(m, __shfl_xor_sync(0xffffffffu, m, off, 16));
        float ex = expf(s - m);
        float den = ex;
        #pragma unroll
        for (int off = 8; off > 0; off >>= 1)
            den += __shfl_xor_sync(0xffffffffu, den, off, 16);
        sAtt[tid] = ex / den;
    }
    __syncthreads();

    // ---------------- phase 4: h_prime, h_edge ----------------
    #pragma unroll
    for (int t = 0; t < 2; t++) {
        int e = tid + t*THREADS;          // 0..511
        int n = e >> 6, c = e & 63;
        const float* at = sAtt + n*S;
        const float* nh = sNbh + n*S*ST_NBH + c;
        float h0 = 0.f, h1 = 0.f;
        #pragma unroll
        for (int s = 0; s < S; s += 2) {
            h0 += at[s]   * nh[s*ST_NBH];
            h1 += at[s+1] * nh[(s+1)*ST_NBH];
        }
        sOut[n*OUTD + D + c] = h0 + h1;
    }
    {
        int n = tid >> 5, c = tid & 31;   // 8 nodes x 32 edge dims = 256
        const float* at = sAtt + n*S;
        const float* ee = sEe + n*S*ST_EE + c;
        float h0 = 0.f, h1 = 0.f;
        #pragma unroll
        for (int s = 0; s < S; s += 2) {
            h0 += at[s]   * ee[s*ST_EE];
            h1 += at[s+1] * ee[(s+1)*ST_EE];
        }
        sOut[n*OUTD + 2*D + c] = h0 + h1;
    }
    __syncthreads();

    // ---------------- phase 5: coalesced output write ----------------
    {
        float4* o4 = reinterpret_cast<float4*>(gOut) + (size_t)node0 * (OUTD/4);
        const float4* s4 = reinterpret_cast<const float4*>(sOut);
        const int lim = vnodes * (OUTD/4);
        for (int i = tid; i < lim; i += THREADS) o4[i] = s4[i];
    }
}

extern "C" void kernel_launch(void* const* d_in, const int* in_sizes, int n_in,
                              void* d_out, int out_size)
{
    const float* gIn = (const float*)d_in[0];   // input      (N, 128)
    const float* gNb = (const float*)d_in[1];   // neigh_feat (N*16, 128)
    const float* gEe = (const float*)d_in[2];   // edge_emb   (N*16, 32)
    const float* gW  = (const float*)d_in[3];   // W  (128, 64)
    const float* gW2 = (const float*)d_in[4];   // W2 (128, 64)
    const float* gA  = (const float*)d_in[5];   // a  (160, 1)
    float* gOut = (float*)d_out;                // (N, 160)

    const int N = in_sizes[0] / IND;

    cudaFuncSetAttribute(gat_fused_kernel,
                         cudaFuncAttributeMaxDynamicSharedMemorySize, SMEM_BYTES);
    const int grid = (N + B - 1) / B;
    gat_fused_kernel<<<grid, THREADS, SMEM_BYTES>>>(gIn, gNb, gEe, gW, gW2, gA, gOut, N);
}

// round 4
// speedup vs baseline: 2.1769x; 1.2436x over previous
#include <cuda_runtime.h>

// EdgeEmbAttentionAggregator — fused GAT aggregation, fp32, round 3.
// 8x8 register tiles on specialized GEMM warps, swizzled smem A tile,
// W2 streamed from L1, accumulator-resident epilogue, smem union aliasing.

namespace {

constexpr int S    = 16;
constexpr int IND  = 128;
constexpr int D    = 64;
constexpr int E    = 32;
constexpr int B    = 8;               // nodes per CTA
constexpr int ROWS = B * S;           // 128
constexpr int THREADS = 256;
constexpr int OUTD = 160;
constexpr float LRELU_ALPHA = 0.8f;

// smem layout (floats)
constexpr int U_FLOATS   = ROWS * 32 * 4;     // 16384: A tile as 128 rows x 32 float4
constexpr int OFF_A      = 0;                  // union base
constexpr int OFF_P      = 0;                  // score partials [128][9]
constexpr int OFF_P2     = 1152;               // h' partials [16][68]
constexpr int OFF_ATT    = 2240;               // attention [128]
constexpr int OFF_AVEC   = U_FLOATS;           // a vector 160
constexpr int OFF_SXA    = OFF_AVEC + OUTD;    // 8
constexpr int OFF_SC     = OFF_SXA + 8;        // 128
constexpr int OFF_OUT    = OFF_SC + ROWS;      // 8*160
constexpr int SMEM_FLOATS = OFF_OUT + B*OUTD;
constexpr int SMEM_BYTES  = SMEM_FLOATS * 4;   // ~72.4 KB

typedef unsigned long long ull;

__device__ __forceinline__ ull ffma2(ull a, ull b, ull c) {
    ull d;
    asm("fma.rn.f32x2 %0, %1, %2, %3;" : "=l"(d) : "l"(a), "l"(b), "l"(c));
    return d;
}
__device__ __forceinline__ ull splat2(float x) {
    ull r;
    asm("mov.b64 %0, {%1, %1};" : "=l"(r) : "f"(x));
    return r;
}
__device__ __forceinline__ float2 unpack2(ull v) {
    float lo, hi;
    asm("mov.b64 {%0, %1}, %2;" : "=f"(lo), "=f"(hi) : "l"(v));
    return make_float2(lo, hi);
}

} // namespace

__global__ void __launch_bounds__(THREADS, 2)
gat_fused_kernel(const float* __restrict__ gIn,
                 const float* __restrict__ gNb,
                 const float* __restrict__ gEe,
                 const float* __restrict__ gW,
                 const float* __restrict__ gW2,
                 const float* __restrict__ gA,
                 float* __restrict__ gOut,
                 int N)
{
    extern __shared__ float sm[];
    float*  sU   = sm;                 // union region
    float4* sA4  = reinterpret_cast<float4*>(sm);
    float*  sP   = sm + OFF_P;         // [128][9]
    float*  sP2  = sm + OFF_P2;        // [16][68]
    float*  sAtt = sm + OFF_ATT;       // [128]
    float*  sAv  = sm + OFF_AVEC;      // a vector
    float*  sSxa = sm + OFF_SXA;
    float*  sSc  = sm + OFF_SC;
    float*  sOut = sm + OFF_OUT;

    const int tid    = threadIdx.x;
    const int node0  = blockIdx.x * B;
    const int vnodes = min(B, N - node0);
    const int vrows  = vnodes * S;

    // ============ P0: a vector, zero sSc, stage swizzled A tile ============
    if (tid < OUTD) sAv[tid] = gA[tid];
    if (tid < ROWS) sSc[tid] = 0.f;
    {
        const float4* nb4 = reinterpret_cast<const float4*>(gNb) + (size_t)node0 * S * 32;
        #pragma unroll
        for (int t = 0; t < 16; t++) {
            int i   = tid + t * THREADS;     // 0..4095
            int row = i >> 5;
            int kq  = i & 31;
            float4 v = (row < vrows) ? nb4[i] : make_float4(0.f, 0.f, 0.f, 0.f);
            sA4[row * 32 + (kq ^ (((row >> 3) & 3) << 1))] = v;
        }
    }
    __syncthreads();

    // ============ P1 ============
    ull acc[8][4];
    int rg = 0, cg = 0;

    if (tid < 128) {
        // ---- big GEMM: rows rg*8..rg*8+7, cols {4cg..4cg+3, 32+4cg..32+4cg+3}
        rg = tid >> 3;
        cg = tid & 7;
        const int key = (rg & 3) << 1;
        #pragma unroll
        for (int i = 0; i < 8; i++)
            #pragma unroll
            for (int j = 0; j < 4; j++) acc[i][j] = 0ull;

        const float4* aBase = sA4 + rg * 8 * 32;
        const float*  w2a   = gW2 + 4 * cg;
        const float*  w2b   = gW2 + 32 + 4 * cg;

        for (int kq = 0; kq < 32; kq++) {
            float4 ar[8];
            const int gsw = kq ^ key;
            #pragma unroll
            for (int i = 0; i < 8; i++) ar[i] = aBase[i * 32 + gsw];

            #pragma unroll
            for (int j = 0; j < 4; j++) {
                const int k = 4 * kq + j;
                const ull* bp  = reinterpret_cast<const ull*>(w2a + k * D);
                const ull* bp2 = reinterpret_cast<const ull*>(w2b + k * D);
                ull B0 = bp[0],  B1 = bp[1];
                ull B2 = bp2[0], B3 = bp2[1];
                #pragma unroll
                for (int i = 0; i < 8; i++) {
                    float a = (j == 0) ? ar[i].x : (j == 1) ? ar[i].y
                            : (j == 2) ? ar[i].z : ar[i].w;
                    ull av = splat2(a);
                    acc[i][0] = ffma2(av, B0, acc[i][0]);
                    acc[i][1] = ffma2(av, B1, acc[i][1]);
                    acc[i][2] = ffma2(av, B2, acc[i][2]);
                    acc[i][3] = ffma2(av, B3, acc[i][3]);
                }
            }
        }
    } else {
        const int t = tid - 128;          // 0..127
        // ---- edge-score partials: sSc[row] += ee[row] . a_e
        {
            const float4* ee4 = reinterpret_cast<const float4*>(gEe) + (size_t)node0 * S * 8;
            const float* aE = sAv + 2 * D;
            #pragma unroll
            for (int it = 0; it < 8; it++) {
                int i   = t + it * 128;   // 0..1023
                int row = i >> 3;
                int ch  = i & 7;
                float4 v = (row < vrows) ? ee4[i] : make_float4(0.f, 0.f, 0.f, 0.f);
                float p = v.x * aE[4*ch] + v.y * aE[4*ch+1]
                        + v.z * aE[4*ch+2] + v.w * aE[4*ch+3];
                atomicAdd(&sSc[row], p);
            }
        }
        // ---- x = input @ W : 16 lanes per node, 4 cols/lane, fused s_x
        {
            const int n   = t >> 4;
            const int l16 = t & 15;
            const int nr  = min(node0 + n, N - 1);
            const float* inRow = gIn + (size_t)nr * IND;
            const float* wp    = gW + 4 * l16;
            ull xa0 = 0ull, xa1 = 0ull;
            #pragma unroll 4
            for (int k = 0; k < IND; k++) {
                const ull* bp = reinterpret_cast<const ull*>(wp + k * D);
                ull av = splat2(inRow[k]);
                xa0 = ffma2(av, bp[0], xa0);
                xa1 = ffma2(av, bp[1], xa1);
            }
            float2 xv0 = unpack2(xa0), xv1 = unpack2(xa1);
            *reinterpret_cast<float4*>(sOut + n * OUTD + 4 * l16) =
                make_float4(xv0.x, xv0.y, xv1.x, xv1.y);
            float part = xv0.x * sAv[4*l16]   + xv0.y * sAv[4*l16+1]
                       + xv1.x * sAv[4*l16+2] + xv1.y * sAv[4*l16+3];
            #pragma unroll
            for (int off = 8; off > 0; off >>= 1)
                part += __shfl_xor_sync(0xffffffffu, part, off, 16);
            if (l16 == 0) sSxa[n] = part;
        }
    }
    __syncthreads();   // A tile dead; union becomes epilogue buffers

    // ============ P2a: score partials from register accs ============
    if (tid < 128) {
        const float* aN0 = sAv + D + 4 * cg;         // cols 4cg..
        const float* aN1 = sAv + D + 32 + 4 * cg;    // cols 32+4cg..
        float a00 = aN0[0], a01 = aN0[1], a02 = aN0[2], a03 = aN0[3];
        float a10 = aN1[0], a11 = aN1[1], a12 = aN1[2], a13 = aN1[3];
        #pragma unroll
        for (int i = 0; i < 8; i++) {
            float2 q0 = unpack2(acc[i][0]);
            float2 q1 = unpack2(acc[i][1]);
            float2 q2 = unpack2(acc[i][2]);
            float2 q3 = unpack2(acc[i][3]);
            float p = q0.x*a00 + q0.y*a01 + q1.x*a02 + q1.y*a03
                    + q2.x*a10 + q2.y*a11 + q3.x*a12 + q3.y*a13;
            sP[(rg * 8 + i) * 9 + cg] = p;
        }
    }
    __syncthreads();

    // ============ P2b: scores -> leaky relu -> softmax (threads 0..127) ============
    if (tid < 128) {
        const int row = tid;
        float s = sSc[row] + sSxa[row >> 4];
        #pragma unroll
        for (int c = 0; c < 8; c++) s += sP[row * 9 + c];
        s = (s > 0.f) ? s : LRELU_ALPHA * s;
        float m = s;
        #pragma unroll
        for (int off = 8; off > 0; off >>= 1)
            m = fmaxf(m, __shfl_xor_sync(0xffffffffu, m, off, 16));
        float ex = expf(s - m);
        float den = ex;
        #pragma unroll
        for (int off = 8; off > 0; off >>= 1)
            den += __shfl_xor_sync(0xffffffffu, den, off, 16);
        sAtt[row] = ex / den;
    }
    __syncthreads();

    // ============ P2c: h' partials (GEMM threads) || h_edge (x threads) ============
    if (tid < 128) {
        ull hp0 = 0ull, hp1 = 0ull, hp2 = 0ull, hp3 = 0ull;
        #pragma unroll
        for (int i = 0; i < 8; i++) {
            ull av = splat2(sAtt[rg * 8 + i]);
            hp0 = ffma2(av, acc[i][0], hp0);
            hp1 = ffma2(av, acc[i][1], hp1);
            hp2 = ffma2(av, acc[i][2], hp2);
            hp3 = ffma2(av, acc[i][3], hp3);
        }
        float2 p0 = unpack2(hp0), p1 = unpack2(hp1);
        float2 p2 = unpack2(hp2), p3 = unpack2(hp3);
        *reinterpret_cast<float4*>(sP2 + rg * 68 + 4 * cg) =
            make_float4(p0.x, p0.y, p1.x, p1.y);
        *reinterpret_cast<float4*>(sP2 + rg * 68 + 32 + 4 * cg) =
            make_float4(p2.x, p2.y, p3.x, p3.y);
    } else {
        const int t  = tid - 128;
        const int n  = t >> 4;
        const int ep = t & 15;            // edge col pair 2ep, 2ep+1
        const float* eb = gEe + ((size_t)(node0 + n) * S) * E + 2 * ep;
        float h0 = 0.f, h1 = 0.f;
        if (n < vnodes) {
            #pragma unroll
            for (int s = 0; s < S; s++) {
                float at = sAtt[n * S + s];
                float2 v = *reinterpret_cast<const float2*>(eb + s * E);
                h0 += at * v.x;
                h1 += at * v.y;
            }
        }
        sOut[n * OUTD + 2 * D + 2 * ep]     = h0;
        sOut[n * OUTD + 2 * D + 2 * ep + 1] = h1;
    }
    __syncthreads();

    // ============ P2d: h' pair-reduce into sOut ============
    {
        int e = tid;                       // 2 x 256 = 512 = 8 nodes x 64 cols
        #pragma unroll
        for (int t = 0; t < 2; t++) {
            int n = e >> 6, c = e & 63;
            sOut[n * OUTD + D + c] = sP2[(2*n) * 68 + c] + sP2[(2*n + 1) * 68 + c];
            e += THREADS;
        }
    }
    __syncthreads();

    // ============ P3: coalesced output ============
    {
        float4* o4 = reinterpret_cast<float4*>(gOut) + (size_t)node0 * (OUTD / 4);
        const float4* s4 = reinterpret_cast<const float4*>(sOut);
        const int lim = vnodes * (OUTD / 4);
        for (int i = tid; i < lim; i += THREADS) o4[i] = s4[i];
    }
}

extern "C" void kernel_launch(void* const* d_in, const int* in_sizes, int n_in,
                              void* d_out, int out_size)
{
    const float* gIn = (const float*)d_in[0];   // input      (N, 128)
    const float* gNb = (const float*)d_in[1];   // neigh_feat (N*16, 128)
    const float* gEe = (const float*)d_in[2];   // edge_emb   (N*16, 32)
    const float* gW  = (const float*)d_in[3];   // W  (128, 64)
    const float* gW2 = (const float*)d_in[4];   // W2 (128, 64)
    const float* gA  = (const float*)d_in[5];   // a  (160, 1)
    float* gOut = (float*)d_out;                // (N, 160)

    const int N = in_sizes[0] / IND;

    cudaFuncSetAttribute(gat_fused_kernel,
                         cudaFuncAttributeMaxDynamicSharedMemorySize, SMEM_BYTES);
    const int grid = (N + B - 1) / B;
    gat_fused_kernel<<<grid, THREADS, SMEM_BYTES>>>(gIn, gNb, gEe, gW, gW2, gA, gOut, N);
}

// round 5
// speedup vs baseline: 2.2081x; 1.0143x over previous
#include <cuda_runtime.h>

// EdgeEmbAttentionAggregator — fused GAT aggregation, fp32, round 4.
// Direct-gmem GEMM (no A staging), 3 CTAs/SM, 256 GEMM threads with 4x8
// tiles, pre-GEMM overlap phase (x-GEMM || edge scores), 3 barriers total.

namespace {

constexpr int S    = 16;
constexpr int IND  = 128;
constexpr int D    = 64;
constexpr int E    = 32;
constexpr int B    = 8;               // nodes per CTA
constexpr int ROWS = B * S;           // 128
constexpr int THREADS = 256;
constexpr int OUTD = 160;
constexpr float LRELU_ALPHA = 0.8f;

typedef unsigned long long ull;

__device__ __forceinline__ ull ffma2(ull a, ull b, ull c) {
    ull d;
    asm("fma.rn.f32x2 %0, %1, %2, %3;" : "=l"(d) : "l"(a), "l"(b), "l"(c));
    return d;
}
__device__ __forceinline__ ull splat2(float x) {
    ull r;
    asm("mov.b64 %0, {%1, %1};" : "=l"(r) : "f"(x));
    return r;
}
__device__ __forceinline__ float2 unpack2(ull v) {
    float lo, hi;
    asm("mov.b64 {%0, %1}, %2;" : "=f"(lo), "=f"(hi) : "l"(v));
    return make_float2(lo, hi);
}

} // namespace

__global__ void __launch_bounds__(THREADS, 3)
gat_fused_kernel(const float* __restrict__ gIn,
                 const float* __restrict__ gNb,
                 const float* __restrict__ gEe,
                 const float* __restrict__ gW,
                 const float* __restrict__ gW2,
                 const float* __restrict__ gA,
                 float* __restrict__ gOut,
                 int N)
{
    __shared__ float sP [ROWS * 9];     // score partials [row][cg]
    __shared__ float sP2[32 * 68];      // h' partials   [rg][col]
    __shared__ float sAtt[ROWS];
    __shared__ float sSc [ROWS];        // edge-score per row
    __shared__ float sSxa[B];           // s_x per node
    __shared__ float sOut[B * OUTD];

    const int tid    = threadIdx.x;
    const int node0  = blockIdx.x * B;
    const int vnodes = min(B, N - node0);
    const int vrows  = vnodes * S;

    // ================= P0: x-GEMM (warps 0-3) || edge scores (warps 4-7) ====
    if (tid < 128) {
        // x = input@W : 16 threads per node, 4 cols each; fused s_x
        const int n    = tid >> 4;          // 0..7
        const int cg16 = tid & 15;          // col group: cols 4*cg16..+3
        const int nr   = min(node0 + n, N - 1);
        const float* inRow = gIn + (size_t)nr * IND;
        const float4* in4  = reinterpret_cast<const float4*>(inRow);
        const float* wp    = gW + 4 * cg16;

        ull x0 = 0ull, x1 = 0ull;
        #pragma unroll 8
        for (int kq = 0; kq < 32; kq++) {
            float4 av4 = __ldg(in4 + kq);
            #pragma unroll
            for (int j = 0; j < 4; j++) {
                const int k = 4 * kq + j;
                const ull* bp = reinterpret_cast<const ull*>(wp + k * D);
                float a = (j == 0) ? av4.x : (j == 1) ? av4.y
                        : (j == 2) ? av4.z : av4.w;
                ull av = splat2(a);
                x0 = ffma2(av, bp[0], x0);
                x1 = ffma2(av, bp[1], x1);
            }
        }
        float2 v0 = unpack2(x0), v1 = unpack2(x1);
        *reinterpret_cast<float4*>(sOut + n * OUTD + 4 * cg16) =
            make_float4(v0.x, v0.y, v1.x, v1.y);

        float4 ax = __ldg(reinterpret_cast<const float4*>(gA + 4 * cg16));
        float part = v0.x * ax.x + v0.y * ax.y + v1.x * ax.z + v1.y * ax.w;
        #pragma unroll
        for (int off = 8; off > 0; off >>= 1)
            part += __shfl_xor_sync(0xffffffffu, part, off, 16);
        if (cg16 == 0) sSxa[n] = part;
    } else {
        // edge-score: 8 threads per row (chunks of 4 floats), shfl-8 combine
        const int t = tid - 128;            // 0..127
        const float4* ee4 = reinterpret_cast<const float4*>(gEe)
                            + (size_t)node0 * S * (E / 4);
        #pragma unroll
        for (int it = 0; it < 8; it++) {
            int i   = t + it * 128;         // 0..1023
            int row = i >> 3;
            int ch  = i & 7;
            float4 v = (row < vrows) ? __ldg(ee4 + i)
                                     : make_float4(0.f, 0.f, 0.f, 0.f);
            float4 ae = __ldg(reinterpret_cast<const float4*>(gA + 2 * D + 4 * ch));
            float p = v.x * ae.x + v.y * ae.y + v.z * ae.z + v.w * ae.w;
            p += __shfl_xor_sync(0xffffffffu, p, 4, 8);
            p += __shfl_xor_sync(0xffffffffu, p, 2, 8);
            p += __shfl_xor_sync(0xffffffffu, p, 1, 8);
            if (ch == 0) sSc[row] = p;
        }
    }

    // ================= P1: neighbor GEMM, direct gmem, 4x8 tiles ============
    const int rg = tid >> 3;                // 0..31 -> rows 4rg..4rg+3
    const int cg = tid & 7;                 // cols {4cg..+3, 32+4cg..+3}

    const float4* ar[4];
    #pragma unroll
    for (int i = 0; i < 4; i++) {
        int r = min(4 * rg + i, vrows - 1);
        ar[i] = reinterpret_cast<const float4*>(
                    gNb + ((size_t)node0 * S + r) * IND);
    }
    const float* w2a = gW2 + 4 * cg;
    const float* w2b = gW2 + 32 + 4 * cg;

    ull acc[4][4];
    #pragma unroll
    for (int i = 0; i < 4; i++)
        #pragma unroll
        for (int j = 0; j < 4; j++) acc[i][j] = 0ull;

    for (int kq = 0; kq < 32; kq++) {
        float4 a0 = __ldg(ar[0] + kq);
        float4 a1 = __ldg(ar[1] + kq);
        float4 a2 = __ldg(ar[2] + kq);
        float4 a3 = __ldg(ar[3] + kq);
        #pragma unroll
        for (int j = 0; j < 4; j++) {
            const int k = 4 * kq + j;
            const ull* bp  = reinterpret_cast<const ull*>(w2a + k * D);
            const ull* bp2 = reinterpret_cast<const ull*>(w2b + k * D);
            ull B0 = bp[0],  B1 = bp[1];
            ull B2 = bp2[0], B3 = bp2[1];
            float e0 = (j==0)?a0.x:(j==1)?a0.y:(j==2)?a0.z:a0.w;
            float e1 = (j==0)?a1.x:(j==1)?a1.y:(j==2)?a1.z:a1.w;
            float e2 = (j==0)?a2.x:(j==1)?a2.y:(j==2)?a2.z:a2.w;
            float e3 = (j==0)?a3.x:(j==1)?a3.y:(j==2)?a3.z:a3.w;
            ull av;
            av = splat2(e0);
            acc[0][0]=ffma2(av,B0,acc[0][0]); acc[0][1]=ffma2(av,B1,acc[0][1]);
            acc[0][2]=ffma2(av,B2,acc[0][2]); acc[0][3]=ffma2(av,B3,acc[0][3]);
            av = splat2(e1);
            acc[1][0]=ffma2(av,B0,acc[1][0]); acc[1][1]=ffma2(av,B1,acc[1][1]);
            acc[1][2]=ffma2(av,B2,acc[1][2]); acc[1][3]=ffma2(av,B3,acc[1][3]);
            av = splat2(e2);
            acc[2][0]=ffma2(av,B0,acc[2][0]); acc[2][1]=ffma2(av,B1,acc[2][1]);
            acc[2][2]=ffma2(av,B2,acc[2][2]); acc[2][3]=ffma2(av,B3,acc[2][3]);
            av = splat2(e3);
            acc[3][0]=ffma2(av,B0,acc[3][0]); acc[3][1]=ffma2(av,B1,acc[3][1]);
            acc[3][2]=ffma2(av,B2,acc[3][2]); acc[3][3]=ffma2(av,B3,acc[3][3]);
        }
    }

    // score partials from accs (a_n straight from L1)
    {
        float4 an0 = __ldg(reinterpret_cast<const float4*>(gA + D + 4 * cg));
        float4 an1 = __ldg(reinterpret_cast<const float4*>(gA + D + 32 + 4 * cg));
        #pragma unroll
        for (int i = 0; i < 4; i++) {
            float2 q0 = unpack2(acc[i][0]);
            float2 q1 = unpack2(acc[i][1]);
            float2 q2 = unpack2(acc[i][2]);
            float2 q3 = unpack2(acc[i][3]);
            float p = q0.x*an0.x + q0.y*an0.y + q1.x*an0.z + q1.y*an0.w
                    + q2.x*an1.x + q2.y*an1.y + q3.x*an1.z + q3.y*an1.w;
            sP[(4 * rg + i) * 9 + cg] = p;
        }
    }
    __syncthreads();

    // ================= P2: scores -> leaky relu -> softmax ==================
    if (tid < ROWS) {
        const int row = tid;
        float s = sSc[row] + sSxa[row >> 4];
        #pragma unroll
        for (int c = 0; c < 8; c++) s += sP[row * 9 + c];
        s = (s > 0.f) ? s : LRELU_ALPHA * s;
        float m = s;
        #pragma unroll
        for (int off = 8; off > 0; off >>= 1)
            m = fmaxf(m, __shfl_xor_sync(0xffffffffu, m, off, 16));
        float ex = expf(s - m);
        float den = ex;
        #pragma unroll
        for (int off = 8; off > 0; off >>= 1)
            den += __shfl_xor_sync(0xffffffffu, den, off, 16);
        sAtt[row] = ex / den;
    }
    __syncthreads();

    // ================= P3: h' partials + h_edge =============================
    {
        ull hp0 = 0ull, hp1 = 0ull, hp2 = 0ull, hp3 = 0ull;
        #pragma unroll
        for (int i = 0; i < 4; i++) {
            ull av = splat2(sAtt[4 * rg + i]);
            hp0 = ffma2(av, acc[i][0], hp0);
            hp1 = ffma2(av, acc[i][1], hp1);
            hp2 = ffma2(av, acc[i][2], hp2);
            hp3 = ffma2(av, acc[i][3], hp3);
        }
        float2 p0 = unpack2(hp0), p1 = unpack2(hp1);
        float2 p2 = unpack2(hp2), p3 = unpack2(hp3);
        *reinterpret_cast<float4*>(sP2 + rg * 68 + 4 * cg) =
            make_float4(p0.x, p0.y, p1.x, p1.y);
        *reinterpret_cast<float4*>(sP2 + rg * 68 + 32 + 4 * cg) =
            make_float4(p2.x, p2.y, p3.x, p3.y);
    }
    {
        // h_edge: 32 threads per node, 1 edge col each; gEe is L1-hot now
        const int n  = tid >> 5;
        const int ep = tid & 31;
        const float* eb = gEe + ((size_t)min(node0 + n, N - 1) * S) * E + ep;
        float h = 0.f;
        #pragma unroll
        for (int s = 0; s < S; s++)
            h += sAtt[n * S + s] * __ldg(eb + s * E);
        sOut[n * OUTD + 2 * D + ep] = h;
    }
    __syncthreads();

    // ================= P4: h' 4-way reduce into sOut ========================
    {
        int e = tid;
        #pragma unroll
        for (int t = 0; t < 2; t++) {       // 512 = 8 nodes x 64 cols
            int n = e >> 6, c = e & 63;
            float h = sP2[(4*n + 0) * 68 + c] + sP2[(4*n + 1) * 68 + c]
                    + sP2[(4*n + 2) * 68 + c] + sP2[(4*n + 3) * 68 + c];
            sOut[n * OUTD + D + c] = h;
            e += THREADS;
        }
    }
    __syncthreads();

    // ================= P5: coalesced output =================================
    {
        float4* o4 = reinterpret_cast<float4*>(gOut) + (size_t)node0 * (OUTD / 4);
        const float4* s4 = reinterpret_cast<const float4*>(sOut);
        const int lim = vnodes * (OUTD / 4);
        for (int i = tid; i < lim; i += THREADS) o4[i] = s4[i];
    }
}

extern "C" void kernel_launch(void* const* d_in, const int* in_sizes, int n_in,
                              void* d_out, int out_size)
{
    const float* gIn = (const float*)d_in[0];   // input      (N, 128)
    const float* gNb = (const float*)d_in[1];   // neigh_feat (N*16, 128)
    const float* gEe = (const float*)d_in[2];   // edge_emb   (N*16, 32)
    const float* gW  = (const float*)d_in[3];   // W  (128, 64)
    const float* gW2 = (const float*)d_in[4];   // W2 (128, 64)
    const float* gA  = (const float*)d_in[5];   // a  (160, 1)
    float* gOut = (float*)d_out;                // (N, 160)

    const int N = in_sizes[0] / IND;
    const int grid = (N + B - 1) / B;
    gat_fused_kernel<<<grid, THREADS>>>(gIn, gNb, gEe, gW, gW2, gA, gOut, N);
}

// round 7
// speedup vs baseline: 2.2179x; 1.0044x over previous
#include <cuda_runtime.h>

// EdgeEmbAttentionAggregator — fused GAT aggregation, fp32, round 5.
// R4 + distance-1 A prefetch (register double-buffer) + B loads as LDG.128.

namespace {

constexpr int S    = 16;
constexpr int IND  = 128;
constexpr int D    = 64;
constexpr int E    = 32;
constexpr int B    = 8;               // nodes per CTA
constexpr int ROWS = B * S;           // 128
constexpr int THREADS = 256;
constexpr int OUTD = 160;
constexpr float LRELU_ALPHA = 0.8f;

typedef unsigned long long ull;

__device__ __forceinline__ ull ffma2(ull a, ull b, ull c) {
    ull d;
    asm("fma.rn.f32x2 %0, %1, %2, %3;" : "=l"(d) : "l"(a), "l"(b), "l"(c));
    return d;
}
__device__ __forceinline__ ull splat2(float x) {
    ull r;
    asm("mov.b64 %0, {%1, %1};" : "=l"(r) : "f"(x));
    return r;
}
__device__ __forceinline__ float2 unpack2(ull v) {
    float lo, hi;
    asm("mov.b64 {%0, %1}, %2;" : "=f"(lo), "=f"(hi) : "l"(v));
    return make_float2(lo, hi);
}

} // namespace

__global__ void __launch_bounds__(THREADS, 3)
gat_fused_kernel(const float* __restrict__ gIn,
                 const float* __restrict__ gNb,
                 const float* __restrict__ gEe,
                 const float* __restrict__ gW,
                 const float* __restrict__ gW2,
                 const float* __restrict__ gA,
                 float* __restrict__ gOut,
                 int N)
{
    __shared__ float sP [ROWS * 9];     // score partials [row][cg]
    __shared__ float sP2[32 * 68];      // h' partials   [rg][col]
    __shared__ float sAtt[ROWS];
    __shared__ float sSc [ROWS];        // edge-score per row
    __shared__ float sSxa[B];           // s_x per node
    __shared__ float sOut[B * OUTD];

    const int tid    = threadIdx.x;
    const int node0  = blockIdx.x * B;
    const int vnodes = min(B, N - node0);
    const int vrows  = vnodes * S;

    // ================= P0: x-GEMM (warps 0-3) || edge scores (warps 4-7) ====
    if (tid < 128) {
        const int n    = tid >> 4;          // 0..7
        const int cg16 = tid & 15;          // cols 4*cg16..+3
        const int nr   = min(node0 + n, N - 1);
        const float4* in4 = reinterpret_cast<const float4*>(gIn + (size_t)nr * IND);
        const float* wp   = gW + 4 * cg16;

        ull x0 = 0ull, x1 = 0ull;
        #pragma unroll 8
        for (int kq = 0; kq < 32; kq++) {
            float4 av4 = __ldg(in4 + kq);
            #pragma unroll
            for (int j = 0; j < 4; j++) {
                const int k = 4 * kq + j;
                ulonglong2 bp = __ldg(reinterpret_cast<const ulonglong2*>(wp + k * D));
                float a = (j == 0) ? av4.x : (j == 1) ? av4.y
                        : (j == 2) ? av4.z : av4.w;
                ull av = splat2(a);
                x0 = ffma2(av, bp.x, x0);
                x1 = ffma2(av, bp.y, x1);
            }
        }
        float2 v0 = unpack2(x0), v1 = unpack2(x1);
        *reinterpret_cast<float4*>(sOut + n * OUTD + 4 * cg16) =
            make_float4(v0.x, v0.y, v1.x, v1.y);

        float4 ax = __ldg(reinterpret_cast<const float4*>(gA + 4 * cg16));
        float part = v0.x * ax.x + v0.y * ax.y + v1.x * ax.z + v1.y * ax.w;
        #pragma unroll
        for (int off = 8; off > 0; off >>= 1)
            part += __shfl_xor_sync(0xffffffffu, part, off, 16);
        if (cg16 == 0) sSxa[n] = part;
    } else {
        const int t = tid - 128;            // 0..127
        const float4* ee4 = reinterpret_cast<const float4*>(gEe)
                            + (size_t)node0 * S * (E / 4);
        #pragma unroll
        for (int it = 0; it < 8; it++) {
            int i   = t + it * 128;         // 0..1023
            int row = i >> 3;
            int ch  = i & 7;
            float4 v = (row < vrows) ? __ldg(ee4 + i)
                                     : make_float4(0.f, 0.f, 0.f, 0.f);
            float4 ae = __ldg(reinterpret_cast<const float4*>(gA + 2 * D + 4 * ch));
            float p = v.x * ae.x + v.y * ae.y + v.z * ae.z + v.w * ae.w;
            p += __shfl_xor_sync(0xffffffffu, p, 4, 8);
            p += __shfl_xor_sync(0xffffffffu, p, 2, 8);
            p += __shfl_xor_sync(0xffffffffu, p, 1, 8);
            if (ch == 0) sSc[row] = p;
        }
    }

    // ================= P1: neighbor GEMM, distance-1 A prefetch =============
    const int rg = tid >> 3;                // rows 4rg..4rg+3
    const int cg = tid & 7;                 // cols {4cg..+3, 32+4cg..+3}

    const float4* ar[4];
    #pragma unroll
    for (int i = 0; i < 4; i++) {
        int r = min(4 * rg + i, vrows - 1);
        ar[i] = reinterpret_cast<const float4*>(
                    gNb + ((size_t)node0 * S + r) * IND);
    }
    const float* w2a = gW2 + 4 * cg;
    const float* w2b = gW2 + 32 + 4 * cg;

    ull acc[4][4];
    #pragma unroll
    for (int i = 0; i < 4; i++)
        #pragma unroll
        for (int j = 0; j < 4; j++) acc[i][j] = 0ull;

    float4 curA[4], nxtA[4];
    #pragma unroll
    for (int i = 0; i < 4; i++) curA[i] = __ldg(ar[i]);

    #pragma unroll 2
    for (int kq = 0; kq < 32; kq++) {
        if (kq < 31) {
            #pragma unroll
            for (int i = 0; i < 4; i++) nxtA[i] = __ldg(ar[i] + kq + 1);
        }
        #pragma unroll
        for (int j = 0; j < 4; j++) {
            const int k = 4 * kq + j;
            ulonglong2 bA = __ldg(reinterpret_cast<const ulonglong2*>(w2a + k * D));
            ulonglong2 bB = __ldg(reinterpret_cast<const ulonglong2*>(w2b + k * D));
            float e0 = (j==0)?curA[0].x:(j==1)?curA[0].y:(j==2)?curA[0].z:curA[0].w;
            float e1 = (j==0)?curA[1].x:(j==1)?curA[1].y:(j==2)?curA[1].z:curA[1].w;
            float e2 = (j==0)?curA[2].x:(j==1)?curA[2].y:(j==2)?curA[2].z:curA[2].w;
            float e3 = (j==0)?curA[3].x:(j==1)?curA[3].y:(j==2)?curA[3].z:curA[3].w;
            ull av;
            av = splat2(e0);
            acc[0][0]=ffma2(av,bA.x,acc[0][0]); acc[0][1]=ffma2(av,bA.y,acc[0][1]);
            acc[0][2]=ffma2(av,bB.x,acc[0][2]); acc[0][3]=ffma2(av,bB.y,acc[0][3]);
            av = splat2(e1);
            acc[1][0]=ffma2(av,bA.x,acc[1][0]); acc[1][1]=ffma2(av,bA.y,acc[1][1]);
            acc[1][2]=ffma2(av,bB.x,acc[1][2]); acc[1][3]=ffma2(av,bB.y,acc[1][3]);
            av = splat2(e2);
            acc[2][0]=ffma2(av,bA.x,acc[2][0]); acc[2][1]=ffma2(av,bA.y,acc[2][1]);
            acc[2][2]=ffma2(av,bB.x,acc[2][2]); acc[2][3]=ffma2(av,bB.y,acc[2][3]);
            av = splat2(e3);
            acc[3][0]=ffma2(av,bA.x,acc[3][0]); acc[3][1]=ffma2(av,bA.y,acc[3][1]);
            acc[3][2]=ffma2(av,bB.x,acc[3][2]); acc[3][3]=ffma2(av,bB.y,acc[3][3]);
        }
        #pragma unroll
        for (int i = 0; i < 4; i++) curA[i] = nxtA[i];
    }

    // score partials from accs
    {
        float4 an0 = __ldg(reinterpret_cast<const float4*>(gA + D + 4 * cg));
        float4 an1 = __ldg(reinterpret_cast<const float4*>(gA + D + 32 + 4 * cg));
        #pragma unroll
        for (int i = 0; i < 4; i++) {
            float2 q0 = unpack2(acc[i][0]);
            float2 q1 = unpack2(acc[i][1]);
            float2 q2 = unpack2(acc[i][2]);
            float2 q3 = unpack2(acc[i][3]);
            float p = q0.x*an0.x + q0.y*an0.y + q1.x*an0.z + q1.y*an0.w
                    + q2.x*an1.x + q2.y*an1.y + q3.x*an1.z + q3.y*an1.w;
            sP[(4 * rg + i) * 9 + cg] = p;
        }
    }
    __syncthreads();

    // ================= P2: scores -> leaky relu -> softmax ==================
    if (tid < ROWS) {
        const int row = tid;
        float s = sSc[row] + sSxa[row >> 4];
        #pragma unroll
        for (int c = 0; c < 8; c++) s += sP[row * 9 + c];
        s = (s > 0.f) ? s : LRELU_ALPHA * s;
        float m = s;
        #pragma unroll
        for (int off = 8; off > 0; off >>= 1)
            m = fmaxf(m, __shfl_xor_sync(0xffffffffu, m, off, 16));
        float ex = expf(s - m);
        float den = ex;
        #pragma unroll
        for (int off = 8; off > 0; off >>= 1)
            den += __shfl_xor_sync(0xffffffffu, den, off, 16);
        sAtt[row] = ex / den;
    }
    __syncthreads();

    // ================= P3: h' partials + h_edge =============================
    {
        ull hp0 = 0ull, hp1 = 0ull, hp2 = 0ull, hp3 = 0ull;
        #pragma unroll
        for (int i = 0; i < 4; i++) {
            ull av = splat2(sAtt[4 * rg + i]);
            hp0 = ffma2(av, acc[i][0], hp0);
            hp1 = ffma2(av, acc[i][1], hp1);
            hp2 = ffma2(av, acc[i][2], hp2);
            hp3 = ffma2(av, acc[i][3], hp3);
        }
        float2 p0 = unpack2(hp0), p1 = unpack2(hp1);
        float2 p2 = unpack2(hp2), p3 = unpack2(hp3);
        *reinterpret_cast<float4*>(sP2 + rg * 68 + 4 * cg) =
            make_float4(p0.x, p0.y, p1.x, p1.y);
        *reinterpret_cast<float4*>(sP2 + rg * 68 + 32 + 4 * cg) =
            make_float4(p2.x, p2.y, p3.x, p3.y);
    }
    {
        const int n  = tid >> 5;
        const int ep = tid & 31;
        const float* eb = gEe + ((size_t)min(node0 + n, N - 1) * S) * E + ep;
        float h = 0.f;
        #pragma unroll
        for (int s = 0; s < S; s++)
            h += sAtt[n * S + s] * __ldg(eb + s * E);
        sOut[n * OUTD + 2 * D + ep] = h;
    }
    __syncthreads();

    // ================= P4: h' 4-way reduce into sOut ========================
    {
        int e = tid;
        #pragma unroll
        for (int t = 0; t < 2; t++) {       // 512 = 8 nodes x 64 cols
            int n = e >> 6, c = e & 63;
            float h = sP2[(4*n + 0) * 68 + c] + sP2[(4*n + 1) * 68 + c]
                    + sP2[(4*n + 2) * 68 + c] + sP2[(4*n + 3) * 68 + c];
            sOut[n * OUTD + D + c] = h;
            e += THREADS;
        }
    }
    __syncthreads();

    // ================= P5: coalesced output =================================
    {
        float4* o4 = reinterpret_cast<float4*>(gOut) + (size_t)node0 * (OUTD / 4);
        const float4* s4 = reinterpret_cast<const float4*>(sOut);
        const int lim = vnodes * (OUTD / 4);
        for (int i = tid; i < lim; i += THREADS) o4[i] = s4[i];
    }
}

extern "C" void kernel_launch(void* const* d_in, const int* in_sizes, int n_in,
                              void* d_out, int out_size)
{
    const float* gIn = (const float*)d_in[0];   // input      (N, 128)
    const float* gNb = (const float*)d_in[1];   // neigh_feat (N*16, 128)
    const float* gEe = (const float*)d_in[2];   // edge_emb   (N*16, 32)
    const float* gW  = (const float*)d_in[3];   // W  (128, 64)
    const float* gW2 = (const float*)d_in[4];   // W2 (128, 64)
    const float* gA  = (const float*)d_in[5];   // a  (160, 1)
    float* gOut = (float*)d_out;                // (N, 160)

    const int N = in_sizes[0] / IND;
    const int grid = (N + B - 1) / B;
    gat_fused_kernel<<<grid, THREADS>>>(gIn, gNb, gEe, gW, gW2, gA, gOut, N);
}

// round 9
// speedup vs baseline: 2.6887x; 1.2123x over previous
#include <cuda_runtime.h>
#include <cstdint>

// EdgeEmbAttentionAggregator — round 9: neighbor GEMM on tensor pipe via
// mma.sync.m16n8k16 bf16 (sm_80 PTX — the harness PTX target is sm_103
// non-'a', so tcgen05 is unavailable). bf16x3 split (Ahi*Bhi + Alo*Bhi +
// Ahi*Blo) for fp32-grade accuracy. A/B pre-split once into swizzled bf16
// smem; ldmatrix fragment loads; register-resident epilogue.

namespace {

constexpr int S    = 16;
constexpr int IND  = 128;
constexpr int D    = 64;
constexpr int E    = 32;
constexpr int B    = 8;
constexpr int ROWS = B * S;            // 128
constexpr int THREADS = 256;
constexpr int OUTD = 160;
constexpr float LRELU_ALPHA = 0.8f;

// dynamic smem offsets (bytes)
constexpr int OFF_AHI = 0;                  // 128 x 128 bf16 = 32768
constexpr int OFF_ALO = 32768;              // 32768
constexpr int OFF_BHI = 65536;              // 128 x 64 bf16 = 16384
constexpr int OFF_BLO = 81920;              // 16384
constexpr int OFF_ATT = 98304;              // 128 f32
constexpr int OFF_SC  = OFF_ATT + 512;      // 128 f32
constexpr int OFF_SXA = OFF_SC  + 512;      // 8 f32
constexpr int OFF_OUT = OFF_SXA + 32;       // 8*160 f32 = 5120
constexpr int SMEM_BYTES = OFF_OUT + 5120;  // 104480

typedef unsigned long long ull;

__device__ __forceinline__ uint32_t smem_u32(const void* p) {
    uint32_t a;
    asm("{ .reg .u64 t; cvta.to.shared.u64 t, %1; cvt.u32.u64 %0, t; }"
        : "=r"(a) : "l"(p));
    return a;
}
__device__ __forceinline__ ull ffma2(ull a, ull b, ull c) {
    ull d;
    asm("fma.rn.f32x2 %0, %1, %2, %3;" : "=l"(d) : "l"(a), "l"(b), "l"(c));
    return d;
}
__device__ __forceinline__ ull splat2(float x) {
    ull r;
    asm("mov.b64 %0, {%1, %1};" : "=l"(r) : "f"(x));
    return r;
}
__device__ __forceinline__ float2 unpack2(ull v) {
    float lo, hi;
    asm("mov.b64 {%0, %1}, %2;" : "=f"(lo), "=f"(hi) : "l"(v));
    return make_float2(lo, hi);
}
// pack: result lo16 = bf16(b), hi16 = bf16(a)  -> memory order (b, a)
__device__ __forceinline__ uint32_t pack_bf16(float a_hi, float b_lo) {
    uint32_t r;
    asm("cvt.rn.bf16x2.f32 %0, %1, %2;" : "=r"(r) : "f"(a_hi), "f"(b_lo));
    return r;
}
__device__ __forceinline__ float bf_lo(uint32_t p) { return __uint_as_float(p << 16); }
__device__ __forceinline__ float bf_hi(uint32_t p) { return __uint_as_float(p & 0xFFFF0000u); }

__device__ __forceinline__ void ldsm_x4(uint32_t addr, uint32_t* r) {
    asm volatile("ldmatrix.sync.aligned.m8n8.x4.shared.b16 {%0,%1,%2,%3}, [%4];"
        : "=r"(r[0]), "=r"(r[1]), "=r"(r[2]), "=r"(r[3]) : "r"(addr));
}
__device__ __forceinline__ void ldsm_x4t(uint32_t addr, uint32_t* r) {
    asm volatile("ldmatrix.sync.aligned.m8n8.x4.trans.shared.b16 {%0,%1,%2,%3}, [%4];"
        : "=r"(r[0]), "=r"(r[1]), "=r"(r[2]), "=r"(r[3]) : "r"(addr));
}
__device__ __forceinline__ void mma_bf16(float* d, const uint32_t* a,
                                         uint32_t b0, uint32_t b1) {
    asm volatile(
        "mma.sync.aligned.m16n8k16.row.col.f32.bf16.bf16.f32 "
        "{%0,%1,%2,%3}, {%4,%5,%6,%7}, {%8,%9}, {%0,%1,%2,%3};"
        : "+f"(d[0]), "+f"(d[1]), "+f"(d[2]), "+f"(d[3])
        : "r"(a[0]), "r"(a[1]), "r"(a[2]), "r"(a[3]), "r"(b0), "r"(b1));
}

} // namespace

__global__ void __launch_bounds__(THREADS, 2)
gat_mma_kernel(const float* __restrict__ gIn,
               const float* __restrict__ gNb,
               const float* __restrict__ gEe,
               const float* __restrict__ gW,
               const float* __restrict__ gW2,
               const float* __restrict__ gA,
               float* __restrict__ gOut,
               int N)
{
    extern __shared__ char smc[];
    float* sAtt = reinterpret_cast<float*>(smc + OFF_ATT);
    float* sSc  = reinterpret_cast<float*>(smc + OFF_SC);
    float* sSxa = reinterpret_cast<float*>(smc + OFF_SXA);
    float* sOut = reinterpret_cast<float*>(smc + OFF_OUT);
    const uint32_t sb = smem_u32(smc);

    const int tid    = threadIdx.x;
    const int node0  = blockIdx.x * B;
    const int vnodes = min(B, N - node0);
    const int vrows  = vnodes * S;

    // ============ P0: split-stage A and B into bf16 hi/lo (swizzled) ========
    {
        // A: 2048 16B-units (128 rows x 16 units of 8 bf16)
        const float4* nb4 = reinterpret_cast<const float4*>(gNb) + (size_t)node0 * S * 32;
        #pragma unroll
        for (int t = 0; t < 8; t++) {
            int idx = tid + t * THREADS;       // 0..2047
            int r = idx >> 4, u = idx & 15;
            float4 fa = make_float4(0.f,0.f,0.f,0.f), fb = fa;
            if (r < vrows) { fa = __ldg(nb4 + r*32 + u*2); fb = __ldg(nb4 + r*32 + u*2 + 1); }
            uint32_t h0 = pack_bf16(fa.y, fa.x), h1 = pack_bf16(fa.w, fa.z);
            uint32_t h2 = pack_bf16(fb.y, fb.x), h3 = pack_bf16(fb.w, fb.z);
            uint32_t l0 = pack_bf16(fa.y - bf_hi(h0), fa.x - bf_lo(h0));
            uint32_t l1 = pack_bf16(fa.w - bf_hi(h1), fa.z - bf_lo(h1));
            uint32_t l2 = pack_bf16(fb.y - bf_hi(h2), fb.x - bf_lo(h2));
            uint32_t l3 = pack_bf16(fb.w - bf_hi(h3), fb.z - bf_lo(h3));
            uint32_t off = r * 256 + ((u ^ (r & 7)) << 4);
            *reinterpret_cast<uint4*>(smc + OFF_AHI + off) = make_uint4(h0,h1,h2,h3);
            *reinterpret_cast<uint4*>(smc + OFF_ALO + off) = make_uint4(l0,l1,l2,l3);
        }
        // B = W2 (128 k-rows x 64 n): 1024 16B-units (8 per row)
        const float4* w24 = reinterpret_cast<const float4*>(gW2);
        #pragma unroll
        for (int t = 0; t < 4; t++) {
            int idx = tid + t * THREADS;       // 0..1023
            int k = idx >> 3, u = idx & 7;
            float4 fa = __ldg(w24 + k*16 + u*2);
            float4 fb = __ldg(w24 + k*16 + u*2 + 1);
            uint32_t h0 = pack_bf16(fa.y, fa.x), h1 = pack_bf16(fa.w, fa.z);
            uint32_t h2 = pack_bf16(fb.y, fb.x), h3 = pack_bf16(fb.w, fb.z);
            uint32_t l0 = pack_bf16(fa.y - bf_hi(h0), fa.x - bf_lo(h0));
            uint32_t l1 = pack_bf16(fa.w - bf_hi(h1), fa.z - bf_lo(h1));
            uint32_t l2 = pack_bf16(fb.y - bf_hi(h2), fb.x - bf_lo(h2));
            uint32_t l3 = pack_bf16(fb.w - bf_hi(h3), fb.z - bf_lo(h3));
            uint32_t off = k * 128 + ((u ^ (k & 7)) << 4);
            *reinterpret_cast<uint4*>(smc + OFF_BHI + off) = make_uint4(h0,h1,h2,h3);
            *reinterpret_cast<uint4*>(smc + OFF_BLO + off) = make_uint4(l0,l1,l2,l3);
        }
    }
    __syncthreads();

    // ============ P1: GEMM (warps 0-3) || x-GEMM + edge scores (4-7) ========
    float acc[2][8][4];
    const int w    = tid >> 5;
    const int lane = tid & 31;
    const int g    = lane >> 2;
    const int tig  = lane & 3;
    const int tsel = lane >> 3;
    const int lr   = lane & 7;
    const int rowoff = ((tsel & 1) << 3) + lr;   // ldmatrix row within 16
    const int uoff   = tsel >> 1;                // ldmatrix 16B-unit offset

    if (tid < 128) {
        #pragma unroll
        for (int m = 0; m < 2; m++)
            #pragma unroll
            for (int nt = 0; nt < 8; nt++)
                #pragma unroll
                for (int j = 0; j < 4; j++) acc[m][nt][j] = 0.f;

        #pragma unroll 2
        for (int ks = 0; ks < 8; ks++) {
            uint32_t ahi[2][4], alo[2][4];
            #pragma unroll
            for (int m = 0; m < 2; m++) {
                int row  = (2*w + m) * 16 + rowoff;
                int unit = 2*ks + uoff;
                uint32_t off = row * 256 + ((unit ^ (row & 7)) << 4);
                ldsm_x4(sb + OFF_AHI + off, ahi[m]);
                ldsm_x4(sb + OFF_ALO + off, alo[m]);
            }
            #pragma unroll
            for (int np = 0; np < 4; np++) {
                int krow = ks * 16 + rowoff;
                int unit = 2*np + uoff;
                uint32_t off = krow * 128 + ((unit ^ (krow & 7)) << 4);
                uint32_t bh[4], bl[4];
                ldsm_x4t(sb + OFF_BHI + off, bh);
                ldsm_x4t(sb + OFF_BLO + off, bl);
                #pragma unroll
                for (int m = 0; m < 2; m++) {
                    mma_bf16(acc[m][2*np],   ahi[m], bh[0], bh[1]);
                    mma_bf16(acc[m][2*np],   alo[m], bh[0], bh[1]);
                    mma_bf16(acc[m][2*np],   ahi[m], bl[0], bl[1]);
                    mma_bf16(acc[m][2*np+1], ahi[m], bh[2], bh[3]);
                    mma_bf16(acc[m][2*np+1], alo[m], bh[2], bh[3]);
                    mma_bf16(acc[m][2*np+1], ahi[m], bl[2], bl[3]);
                }
            }
        }
    } else {
        // ---- x = input @ W (16 lanes/node, 4 cols each) + fused s_x ----
        const int t    = tid - 128;
        const int n    = t >> 4;
        const int cg16 = t & 15;
        const int nr   = min(node0 + n, N - 1);
        const float4* in4 = reinterpret_cast<const float4*>(gIn + (size_t)nr * IND);
        const float* wp   = gW + 4 * cg16;

        ull x0 = 0ull, x1 = 0ull;
        #pragma unroll 8
        for (int kq = 0; kq < 32; kq++) {
            float4 av4 = __ldg(in4 + kq);
            #pragma unroll
            for (int j = 0; j < 4; j++) {
                const int k = 4 * kq + j;
                ulonglong2 bp = __ldg(reinterpret_cast<const ulonglong2*>(wp + k * D));
                float a = (j == 0) ? av4.x : (j == 1) ? av4.y
                        : (j == 2) ? av4.z : av4.w;
                ull av = splat2(a);
                x0 = ffma2(av, bp.x, x0);
                x1 = ffma2(av, bp.y, x1);
            }
        }
        float2 v0 = unpack2(x0), v1 = unpack2(x1);
        *reinterpret_cast<float4*>(sOut + n * OUTD + 4 * cg16) =
            make_float4(v0.x, v0.y, v1.x, v1.y);

        float4 ax = __ldg(reinterpret_cast<const float4*>(gA + 4 * cg16));
        float part = v0.x * ax.x + v0.y * ax.y + v1.x * ax.z + v1.y * ax.w;
        #pragma unroll
        for (int off = 8; off > 0; off >>= 1)
            part += __shfl_xor_sync(0xffffffffu, part, off, 16);
        if (cg16 == 0) sSxa[n] = part;

        // ---- edge scores ----
        const float4* ee4 = reinterpret_cast<const float4*>(gEe)
                            + (size_t)node0 * S * (E / 4);
        #pragma unroll
        for (int it = 0; it < 8; it++) {
            int i   = t + it * 128;
            int row = i >> 3;
            int ch  = i & 7;
            float4 v = (row < vrows) ? __ldg(ee4 + i)
                                     : make_float4(0.f, 0.f, 0.f, 0.f);
            float4 ae = __ldg(reinterpret_cast<const float4*>(gA + 2 * D + 4 * ch));
            float p = v.x * ae.x + v.y * ae.y + v.z * ae.z + v.w * ae.w;
            p += __shfl_xor_sync(0xffffffffu, p, 4, 8);
            p += __shfl_xor_sync(0xffffffffu, p, 2, 8);
            p += __shfl_xor_sync(0xffffffffu, p, 1, 8);
            if (ch == 0) sSc[row] = p;
        }
    }
    __syncthreads();

    // ============ P2: register-resident scores/softmax/h' (GEMM warps) =====
    if (tid < 128) {
        // a_n columns owned by this lane: {8nt+2tig, 8nt+2tig+1}
        float wN[8][2];
        #pragma unroll
        for (int nt = 0; nt < 8; nt++) {
            wN[nt][0] = __ldg(gA + D + 8*nt + 2*tig);
            wN[nt][1] = __ldg(gA + D + 8*nt + 2*tig + 1);
        }
        #pragma unroll
        for (int m = 0; m < 2; m++) {
            const int nd = 2*w + m;
            const int R  = nd * 16;
            float pa = 0.f, pb = 0.f;
            #pragma unroll
            for (int nt = 0; nt < 8; nt++) {
                pa += acc[m][nt][0]*wN[nt][0] + acc[m][nt][1]*wN[nt][1];
                pb += acc[m][nt][2]*wN[nt][0] + acc[m][nt][3]*wN[nt][1];
            }
            pa += __shfl_xor_sync(0xffffffffu, pa, 1);
            pa += __shfl_xor_sync(0xffffffffu, pa, 2);
            pb += __shfl_xor_sync(0xffffffffu, pb, 1);
            pb += __shfl_xor_sync(0xffffffffu, pb, 2);

            float sa = pa + sSc[R + g]     + sSxa[nd];
            float sbv = pb + sSc[R + g + 8] + sSxa[nd];
            sa  = (sa  > 0.f) ? sa  : LRELU_ALPHA * sa;
            sbv = (sbv > 0.f) ? sbv : LRELU_ALPHA * sbv;

            float mx = fmaxf(sa, sbv);
            #pragma unroll
            for (int off = 4; off <= 16; off <<= 1)
                mx = fmaxf(mx, __shfl_xor_sync(0xffffffffu, mx, off));
            float ea = expf(sa - mx), eb = expf(sbv - mx);
            float den = ea + eb;
            #pragma unroll
            for (int off = 4; off <= 16; off <<= 1)
                den += __shfl_xor_sync(0xffffffffu, den, off);
            float inv = 1.f / den;
            float ata = ea * inv, atb = eb * inv;
            if (tig == 0) { sAtt[R + g] = ata; sAtt[R + g + 8] = atb; }

            // h' = att-weighted rows, butterfly-reduced over g
            float h[8][2];
            #pragma unroll
            for (int nt = 0; nt < 8; nt++) {
                h[nt][0] = ata * acc[m][nt][0] + atb * acc[m][nt][2];
                h[nt][1] = ata * acc[m][nt][1] + atb * acc[m][nt][3];
            }
            #pragma unroll
            for (int off = 4; off <= 16; off <<= 1)
                #pragma unroll
                for (int nt = 0; nt < 8; nt++) {
                    h[nt][0] += __shfl_xor_sync(0xffffffffu, h[nt][0], off);
                    h[nt][1] += __shfl_xor_sync(0xffffffffu, h[nt][1], off);
                }
            if (g == 0) {
                #pragma unroll
                for (int nt = 0; nt < 8; nt++)
                    *reinterpret_cast<float2*>(sOut + nd*OUTD + D + 8*nt + 2*tig) =
                        make_float2(h[nt][0], h[nt][1]);
            }
        }
    }
    __syncthreads();

    // ============ P3: h_edge (all 256 threads, 1 col each) ==================
    {
        const int n  = tid >> 5;
        const int ep = tid & 31;
        const float* eb = gEe + ((size_t)min(node0 + n, N - 1) * S) * E + ep;
        float h = 0.f;
        #pragma unroll
        for (int s = 0; s < S; s++)
            h += sAtt[n * S + s] * __ldg(eb + s * E);
        sOut[n * OUTD + 2 * D + ep] = h;
    }
    __syncthreads();

    // ============ P4: coalesced output ======================================
    {
        float4* o4 = reinterpret_cast<float4*>(gOut) + (size_t)node0 * (OUTD / 4);
        const float4* s4 = reinterpret_cast<const float4*>(sOut);
        const int lim = vnodes * (OUTD / 4);
        for (int i = tid; i < lim; i += THREADS) o4[i] = s4[i];
    }
}

extern "C" void kernel_launch(void* const* d_in, const int* in_sizes, int n_in,
                              void* d_out, int out_size)
{
    const float* gIn = (const float*)d_in[0];   // input      (N, 128)
    const float* gNb = (const float*)d_in[1];   // neigh_feat (N*16, 128)
    const float* gEe = (const float*)d_in[2];   // edge_emb   (N*16, 32)
    const float* gW  = (const float*)d_in[3];   // W  (128, 64)
    const float* gW2 = (const float*)d_in[4];   // W2 (128, 64)
    const float* gA  = (const float*)d_in[5];   // a  (160, 1)
    float* gOut = (float*)d_out;                // (N, 160)

    const int N = in_sizes[0] / IND;

    cudaFuncSetAttribute(gat_mma_kernel,
                         cudaFuncAttributeMaxDynamicSharedMemorySize, SMEM_BYTES);
    const int grid = (N + B - 1) / B;
    gat_mma_kernel<<<grid, THREADS, SMEM_BYTES>>>(gIn, gNb, gEe, gW, gW2, gA, gOut, N);
}

// round 10
// speedup vs baseline: 3.7414x; 1.3915x over previous
#include <cuda_runtime.h>
#include <cstdint>

// EdgeEmbAttentionAggregator — round 10: R9 (bf16x3 mma.sync GEMM) with the
// MMA issue order restructured term-major within np-pairs so dependent
// accumulator writes are 8 independent HMMAs apart (was distance 1 -> RAW
// stall on 2 of every 3 MMAs).

namespace {

constexpr int S    = 16;
constexpr int IND  = 128;
constexpr int D    = 64;
constexpr int E    = 32;
constexpr int B    = 8;
constexpr int ROWS = B * S;            // 128
constexpr int THREADS = 256;
constexpr int OUTD = 160;
constexpr float LRELU_ALPHA = 0.8f;

// dynamic smem offsets (bytes)
constexpr int OFF_AHI = 0;                  // 128 x 128 bf16 = 32768
constexpr int OFF_ALO = 32768;              // 32768
constexpr int OFF_BHI = 65536;              // 128 x 64 bf16 = 16384
constexpr int OFF_BLO = 81920;              // 16384
constexpr int OFF_ATT = 98304;              // 128 f32
constexpr int OFF_SC  = OFF_ATT + 512;      // 128 f32
constexpr int OFF_SXA = OFF_SC  + 512;      // 8 f32
constexpr int OFF_OUT = OFF_SXA + 32;       // 8*160 f32 = 5120
constexpr int SMEM_BYTES = OFF_OUT + 5120;  // 104480

typedef unsigned long long ull;

__device__ __forceinline__ uint32_t smem_u32(const void* p) {
    uint32_t a;
    asm("{ .reg .u64 t; cvta.to.shared.u64 t, %1; cvt.u32.u64 %0, t; }"
        : "=r"(a) : "l"(p));
    return a;
}
__device__ __forceinline__ ull ffma2(ull a, ull b, ull c) {
    ull d;
    asm("fma.rn.f32x2 %0, %1, %2, %3;" : "=l"(d) : "l"(a), "l"(b), "l"(c));
    return d;
}
__device__ __forceinline__ ull splat2(float x) {
    ull r;
    asm("mov.b64 %0, {%1, %1};" : "=l"(r) : "f"(x));
    return r;
}
__device__ __forceinline__ float2 unpack2(ull v) {
    float lo, hi;
    asm("mov.b64 {%0, %1}, %2;" : "=f"(lo), "=f"(hi) : "l"(v));
    return make_float2(lo, hi);
}
// pack: result lo16 = bf16(b), hi16 = bf16(a)  -> memory order (b, a)
__device__ __forceinline__ uint32_t pack_bf16(float a_hi, float b_lo) {
    uint32_t r;
    asm("cvt.rn.bf16x2.f32 %0, %1, %2;" : "=r"(r) : "f"(a_hi), "f"(b_lo));
    return r;
}
__device__ __forceinline__ float bf_lo(uint32_t p) { return __uint_as_float(p << 16); }
__device__ __forceinline__ float bf_hi(uint32_t p) { return __uint_as_float(p & 0xFFFF0000u); }

__device__ __forceinline__ void ldsm_x4(uint32_t addr, uint32_t* r) {
    asm volatile("ldmatrix.sync.aligned.m8n8.x4.shared.b16 {%0,%1,%2,%3}, [%4];"
        : "=r"(r[0]), "=r"(r[1]), "=r"(r[2]), "=r"(r[3]) : "r"(addr));
}
__device__ __forceinline__ void ldsm_x4t(uint32_t addr, uint32_t* r) {
    asm volatile("ldmatrix.sync.aligned.m8n8.x4.trans.shared.b16 {%0,%1,%2,%3}, [%4];"
        : "=r"(r[0]), "=r"(r[1]), "=r"(r[2]), "=r"(r[3]) : "r"(addr));
}
__device__ __forceinline__ void mma_bf16(float* d, const uint32_t* a,
                                         uint32_t b0, uint32_t b1) {
    asm volatile(
        "mma.sync.aligned.m16n8k16.row.col.f32.bf16.bf16.f32 "
        "{%0,%1,%2,%3}, {%4,%5,%6,%7}, {%8,%9}, {%0,%1,%2,%3};"
        : "+f"(d[0]), "+f"(d[1]), "+f"(d[2]), "+f"(d[3])
        : "r"(a[0]), "r"(a[1]), "r"(a[2]), "r"(a[3]), "r"(b0), "r"(b1));
}

} // namespace

__global__ void __launch_bounds__(THREADS, 2)
gat_mma_kernel(const float* __restrict__ gIn,
               const float* __restrict__ gNb,
               const float* __restrict__ gEe,
               const float* __restrict__ gW,
               const float* __restrict__ gW2,
               const float* __restrict__ gA,
               float* __restrict__ gOut,
               int N)
{
    extern __shared__ char smc[];
    float* sAtt = reinterpret_cast<float*>(smc + OFF_ATT);
    float* sSc  = reinterpret_cast<float*>(smc + OFF_SC);
    float* sSxa = reinterpret_cast<float*>(smc + OFF_SXA);
    float* sOut = reinterpret_cast<float*>(smc + OFF_OUT);
    const uint32_t sb = smem_u32(smc);

    const int tid    = threadIdx.x;
    const int node0  = blockIdx.x * B;
    const int vnodes = min(B, N - node0);
    const int vrows  = vnodes * S;

    // ============ P0: split-stage A and B into bf16 hi/lo (swizzled) ========
    {
        const float4* nb4 = reinterpret_cast<const float4*>(gNb) + (size_t)node0 * S * 32;
        #pragma unroll
        for (int t = 0; t < 8; t++) {
            int idx = tid + t * THREADS;       // 0..2047
            int r = idx >> 4, u = idx & 15;
            float4 fa = make_float4(0.f,0.f,0.f,0.f), fb = fa;
            if (r < vrows) { fa = __ldg(nb4 + r*32 + u*2); fb = __ldg(nb4 + r*32 + u*2 + 1); }
            uint32_t h0 = pack_bf16(fa.y, fa.x), h1 = pack_bf16(fa.w, fa.z);
            uint32_t h2 = pack_bf16(fb.y, fb.x), h3 = pack_bf16(fb.w, fb.z);
            uint32_t l0 = pack_bf16(fa.y - bf_hi(h0), fa.x - bf_lo(h0));
            uint32_t l1 = pack_bf16(fa.w - bf_hi(h1), fa.z - bf_lo(h1));
            uint32_t l2 = pack_bf16(fb.y - bf_hi(h2), fb.x - bf_lo(h2));
            uint32_t l3 = pack_bf16(fb.w - bf_hi(h3), fb.z - bf_lo(h3));
            uint32_t off = r * 256 + ((u ^ (r & 7)) << 4);
            *reinterpret_cast<uint4*>(smc + OFF_AHI + off) = make_uint4(h0,h1,h2,h3);
            *reinterpret_cast<uint4*>(smc + OFF_ALO + off) = make_uint4(l0,l1,l2,l3);
        }
        const float4* w24 = reinterpret_cast<const float4*>(gW2);
        #pragma unroll
        for (int t = 0; t < 4; t++) {
            int idx = tid + t * THREADS;       // 0..1023
            int k = idx >> 3, u = idx & 7;
            float4 fa = __ldg(w24 + k*16 + u*2);
            float4 fb = __ldg(w24 + k*16 + u*2 + 1);
            uint32_t h0 = pack_bf16(fa.y, fa.x), h1 = pack_bf16(fa.w, fa.z);
            uint32_t h2 = pack_bf16(fb.y, fb.x), h3 = pack_bf16(fb.w, fb.z);
            uint32_t l0 = pack_bf16(fa.y - bf_hi(h0), fa.x - bf_lo(h0));
            uint32_t l1 = pack_bf16(fa.w - bf_hi(h1), fa.z - bf_lo(h1));
            uint32_t l2 = pack_bf16(fb.y - bf_hi(h2), fb.x - bf_lo(h2));
            uint32_t l3 = pack_bf16(fb.w - bf_hi(h3), fb.z - bf_lo(h3));
            uint32_t off = k * 128 + ((u ^ (k & 7)) << 4);
            *reinterpret_cast<uint4*>(smc + OFF_BHI + off) = make_uint4(h0,h1,h2,h3);
            *reinterpret_cast<uint4*>(smc + OFF_BLO + off) = make_uint4(l0,l1,l2,l3);
        }
    }
    __syncthreads();

    // ============ P1: GEMM (warps 0-3) || x-GEMM + edge scores (4-7) ========
    float acc[2][8][4];
    const int w    = tid >> 5;
    const int lane = tid & 31;
    const int g    = lane >> 2;
    const int tig  = lane & 3;
    const int tsel = lane >> 3;
    const int lr   = lane & 7;
    const int rowoff = ((tsel & 1) << 3) + lr;   // ldmatrix row within 16
    const int uoff   = tsel >> 1;                // ldmatrix 16B-unit offset

    if (tid < 128) {
        #pragma unroll
        for (int m = 0; m < 2; m++)
            #pragma unroll
            for (int nt = 0; nt < 8; nt++)
                #pragma unroll
                for (int j = 0; j < 4; j++) acc[m][nt][j] = 0.f;

        #pragma unroll 2
        for (int ks = 0; ks < 8; ks++) {
            uint32_t ahi[2][4], alo[2][4];
            #pragma unroll
            for (int m = 0; m < 2; m++) {
                int row  = (2*w + m) * 16 + rowoff;
                int unit = 2*ks + uoff;
                uint32_t off = row * 256 + ((unit ^ (row & 7)) << 4);
                ldsm_x4(sb + OFF_AHI + off, ahi[m]);
                ldsm_x4(sb + OFF_ALO + off, alo[m]);
            }
            // np-pairs: load B fragments for 2 np, then issue term-major so
            // dependent writes to one accumulator are 8 independent MMAs apart
            #pragma unroll
            for (int hp = 0; hp < 2; hp++) {
                uint32_t bh[2][4], bl[2][4];
                #pragma unroll
                for (int p = 0; p < 2; p++) {
                    int np   = 2*hp + p;
                    int krow = ks * 16 + rowoff;
                    int unit = 2*np + uoff;
                    uint32_t off = krow * 128 + ((unit ^ (krow & 7)) << 4);
                    ldsm_x4t(sb + OFF_BHI + off, bh[p]);
                    ldsm_x4t(sb + OFF_BLO + off, bl[p]);
                }
                // term 0: Ahi * Bhi  (8 independent MMAs)
                #pragma unroll
                for (int p = 0; p < 2; p++) {
                    int np = 2*hp + p;
                    #pragma unroll
                    for (int m = 0; m < 2; m++) {
                        mma_bf16(acc[m][2*np],   ahi[m], bh[p][0], bh[p][1]);
                        mma_bf16(acc[m][2*np+1], ahi[m], bh[p][2], bh[p][3]);
                    }
                }
                // term 1: Alo * Bhi
                #pragma unroll
                for (int p = 0; p < 2; p++) {
                    int np = 2*hp + p;
                    #pragma unroll
                    for (int m = 0; m < 2; m++) {
                        mma_bf16(acc[m][2*np],   alo[m], bh[p][0], bh[p][1]);
                        mma_bf16(acc[m][2*np+1], alo[m], bh[p][2], bh[p][3]);
                    }
                }
                // term 2: Ahi * Blo
                #pragma unroll
                for (int p = 0; p < 2; p++) {
                    int np = 2*hp + p;
                    #pragma unroll
                    for (int m = 0; m < 2; m++) {
                        mma_bf16(acc[m][2*np],   ahi[m], bl[p][0], bl[p][1]);
                        mma_bf16(acc[m][2*np+1], ahi[m], bl[p][2], bl[p][3]);
                    }
                }
            }
        }
    } else {
        // ---- x = input @ W (16 lanes/node, 4 cols each) + fused s_x ----
        const int t    = tid - 128;
        const int n    = t >> 4;
        const int cg16 = t & 15;
        const int nr   = min(node0 + n, N - 1);
        const float4* in4 = reinterpret_cast<const float4*>(gIn + (size_t)nr * IND);
        const float* wp   = gW + 4 * cg16;

        ull x0 = 0ull, x1 = 0ull;
        #pragma unroll 8
        for (int kq = 0; kq < 32; kq++) {
            float4 av4 = __ldg(in4 + kq);
            #pragma unroll
            for (int j = 0; j < 4; j++) {
                const int k = 4 * kq + j;
                ulonglong2 bp = __ldg(reinterpret_cast<const ulonglong2*>(wp + k * D));
                float a = (j == 0) ? av4.x : (j == 1) ? av4.y
                        : (j == 2) ? av4.z : av4.w;
                ull av = splat2(a);
                x0 = ffma2(av, bp.x, x0);
                x1 = ffma2(av, bp.y, x1);
            }
        }
        float2 v0 = unpack2(x0), v1 = unpack2(x1);
        *reinterpret_cast<float4*>(sOut + n * OUTD + 4 * cg16) =
            make_float4(v0.x, v0.y, v1.x, v1.y);

        float4 ax = __ldg(reinterpret_cast<const float4*>(gA + 4 * cg16));
        float part = v0.x * ax.x + v0.y * ax.y + v1.x * ax.z + v1.y * ax.w;
        #pragma unroll
        for (int off = 8; off > 0; off >>= 1)
            part += __shfl_xor_sync(0xffffffffu, part, off, 16);
        if (cg16 == 0) sSxa[n] = part;

        // ---- edge scores ----
        const float4* ee4 = reinterpret_cast<const float4*>(gEe)
                            + (size_t)node0 * S * (E / 4);
        #pragma unroll
        for (int it = 0; it < 8; it++) {
            int i   = t + it * 128;
            int row = i >> 3;
            int ch  = i & 7;
            float4 v = (row < vrows) ? __ldg(ee4 + i)
                                     : make_float4(0.f, 0.f, 0.f, 0.f);
            float4 ae = __ldg(reinterpret_cast<const float4*>(gA + 2 * D + 4 * ch));
            float p = v.x * ae.x + v.y * ae.y + v.z * ae.z + v.w * ae.w;
            p += __shfl_xor_sync(0xffffffffu, p, 4, 8);
            p += __shfl_xor_sync(0xffffffffu, p, 2, 8);
            p += __shfl_xor_sync(0xffffffffu, p, 1, 8);
            if (ch == 0) sSc[row] = p;
        }
    }
    __syncthreads();

    // ============ P2: register-resident scores/softmax/h' (GEMM warps) =====
    if (tid < 128) {
        float wN[8][2];
        #pragma unroll
        for (int nt = 0; nt < 8; nt++) {
            wN[nt][0] = __ldg(gA + D + 8*nt + 2*tig);
            wN[nt][1] = __ldg(gA + D + 8*nt + 2*tig + 1);
        }
        #pragma unroll
        for (int m = 0; m < 2; m++) {
            const int nd = 2*w + m;
            const int R  = nd * 16;
            float pa = 0.f, pb = 0.f;
            #pragma unroll
            for (int nt = 0; nt < 8; nt++) {
                pa += acc[m][nt][0]*wN[nt][0] + acc[m][nt][1]*wN[nt][1];
                pb += acc[m][nt][2]*wN[nt][0] + acc[m][nt][3]*wN[nt][1];
            }
            pa += __shfl_xor_sync(0xffffffffu, pa, 1);
            pa += __shfl_xor_sync(0xffffffffu, pa, 2);
            pb += __shfl_xor_sync(0xffffffffu, pb, 1);
            pb += __shfl_xor_sync(0xffffffffu, pb, 2);

            float sa = pa + sSc[R + g]     + sSxa[nd];
            float sbv = pb + sSc[R + g + 8] + sSxa[nd];
            sa  = (sa  > 0.f) ? sa  : LRELU_ALPHA * sa;
            sbv = (sbv > 0.f) ? sbv : LRELU_ALPHA * sbv;

            float mx = fmaxf(sa, sbv);
            #pragma unroll
            for (int off = 4; off <= 16; off <<= 1)
                mx = fmaxf(mx, __shfl_xor_sync(0xffffffffu, mx, off));
            float ea = expf(sa - mx), eb = expf(sbv - mx);
            float den = ea + eb;
            #pragma unroll
            for (int off = 4; off <= 16; off <<= 1)
                den += __shfl_xor_sync(0xffffffffu, den, off);
            float inv = 1.f / den;
            float ata = ea * inv, atb = eb * inv;
            if (tig == 0) { sAtt[R + g] = ata; sAtt[R + g + 8] = atb; }

            float h[8][2];
            #pragma unroll
            for (int nt = 0; nt < 8; nt++) {
                h[nt][0] = ata * acc[m][nt][0] + atb * acc[m][nt][2];
                h[nt][1] = ata * acc[m][nt][1] + atb * acc[m][nt][3];
            }
            #pragma unroll
            for (int off = 4; off <= 16; off <<= 1)
                #pragma unroll
                for (int nt = 0; nt < 8; nt++) {
                    h[nt][0] += __shfl_xor_sync(0xffffffffu, h[nt][0], off);
                    h[nt][1] += __shfl_xor_sync(0xffffffffu, h[nt][1], off);
                }
            if (g == 0) {
                #pragma unroll
                for (int nt = 0; nt < 8; nt++)
                    *reinterpret_cast<float2*>(sOut + nd*OUTD + D + 8*nt + 2*tig) =
                        make_float2(h[nt][0], h[nt][1]);
            }
        }
    }
    __syncthreads();

    // ============ P3: h_edge (all 256 threads, 1 col each) ==================
    {
        const int n  = tid >> 5;
        const int ep = tid & 31;
        const float* eb = gEe + ((size_t)min(node0 + n, N - 1) * S) * E + ep;
        float h = 0.f;
        #pragma unroll
        for (int s = 0; s < S; s++)
            h += sAtt[n * S + s] * __ldg(eb + s * E);
        sOut[n * OUTD + 2 * D + ep] = h;
    }
    __syncthreads();

    // ============ P4: coalesced output ======================================
    {
        float4* o4 = reinterpret_cast<float4*>(gOut) + (size_t)node0 * (OUTD / 4);
        const float4* s4 = reinterpret_cast<const float4*>(sOut);
        const int lim = vnodes * (OUTD / 4);
        for (int i = tid; i < lim; i += THREADS) o4[i] = s4[i];
    }
}

extern "C" void kernel_launch(void* const* d_in, const int* in_sizes, int n_in,
                              void* d_out, int out_size)
{
    const float* gIn = (const float*)d_in[0];   // input      (N, 128)
    const float* gNb = (const float*)d_in[1];   // neigh_feat (N*16, 128)
    const float* gEe = (const float*)d_in[2];   // edge_emb   (N*16, 32)
    const float* gW  = (const float*)d_in[3];   // W  (128, 64)
    const float* gW2 = (const float*)d_in[4];   // W2 (128, 64)
    const float* gA  = (const float*)d_in[5];   // a  (160, 1)
    float* gOut = (float*)d_out;                // (N, 160)

    const int N = in_sizes[0] / IND;

    cudaFuncSetAttribute(gat_mma_kernel,
                         cudaFuncAttributeMaxDynamicSharedMemorySize, SMEM_BYTES);
    const int grid = (N + B - 1) / B;
    gat_mma_kernel<<<grid, THREADS, SMEM_BYTES>>>(gIn, gNb, gEe, gW, gW2, gA, gOut, N);
}